// round 2
// baseline (speedup 1.0000x reference)
#include <cuda_runtime.h>
#include <cuda_bf16.h>
#include <math.h>

#define NROWS 50001
#define STOPIDX 50000
#define NEGF (-1e18f)
#define TSTEPS 16
#define PB 592  // pass-kernel blocks (4 per SM on 148 SMs)

// ------------------------------------------------------------------
// Static device state (no allocations allowed)
// ------------------------------------------------------------------
__device__ __align__(16) float g_feat_a[NROWS * 512];          // mem @ attn_wm
__device__ __align__(16) float g_feat_h[NROWS * 512];          // mem @ hop_wm
__device__ __align__(16) __nv_bfloat16 g_BtHi[1024 * 512];     // combined W^T hi (n-major)
__device__ __align__(16) __nv_bfloat16 g_BtLo[1024 * 512];     // combined W^T lo
__device__ __align__(16) float g_wqT_attn[512 * 512];          // attn_wq^T (n-major)
__device__ __align__(16) float g_wqT_hop[512 * 512];           // hop_wq^T
__device__ __align__(16) float g_h[512];
__device__ __align__(16) float g_c[2][512];
__device__ __align__(16) float g_x[512];
__device__ __align__(16) float g_gates[2048];
__device__ __align__(16) float g_qw[512];                      // h @ hop_wq
__device__ __align__(16) float g_qw2[512];                     // q2 @ attn_wq
__device__ __align__(16) float g_pvec[PB * 512];
__device__ float g_pmu[PB];
__device__ float g_psum[PB];
__device__ unsigned char g_sel[NROWS];
__device__ unsigned g_hopmax;
__device__ unsigned g_scoremax;
__device__ unsigned long long g_argmax;
__device__ int g_done;

// ------------------------------------------------------------------
// Helpers
// ------------------------------------------------------------------
__device__ __forceinline__ unsigned ford(float f) {
    unsigned u = __float_as_uint(f);
    return (u & 0x80000000u) ? ~u : (u | 0x80000000u);
}
__device__ __forceinline__ float funord(unsigned u) {
    return (u & 0x80000000u) ? __uint_as_float(u & 0x7FFFFFFFu) : __uint_as_float(~u);
}
__device__ __forceinline__ float fast_tanh(float x) {
    float e = __expf(2.0f * x);
    return 1.0f - __fdividef(2.0f, e + 1.0f);
}
__device__ __forceinline__ float fast_sig(float x) {
    return __fdividef(1.0f, 1.0f + __expf(-x));
}
__device__ __forceinline__ float dot_tanh4(float4 f, float4 q, float4 v) {
    return fast_tanh(f.x + q.x) * v.x + fast_tanh(f.y + q.y) * v.y +
           fast_tanh(f.z + q.z) * v.z + fast_tanh(f.w + q.w) * v.w;
}
__device__ __forceinline__ float warp_sum(float s) {
    #pragma unroll
    for (int o = 16; o; o >>= 1) s += __shfl_xor_sync(0xFFFFFFFFu, s, o);
    return s;
}
__device__ __forceinline__ void mma_bf16(float c[4], const unsigned a[4], const unsigned b[2]) {
    asm volatile(
        "mma.sync.aligned.m16n8k16.row.col.f32.bf16.bf16.f32 "
        "{%0,%1,%2,%3},{%4,%5,%6,%7},{%8,%9},{%0,%1,%2,%3};"
        : "+f"(c[0]), "+f"(c[1]), "+f"(c[2]), "+f"(c[3])
        : "r"(a[0]), "r"(a[1]), "r"(a[2]), "r"(a[3]), "r"(b[0]), "r"(b[1]));
}

// ------------------------------------------------------------------
// Init: transpose/split weights, reset state
// ------------------------------------------------------------------
__global__ void kg_init(const float* __restrict__ attn_wq, const float* __restrict__ hop_wq,
                        const float* __restrict__ attn_wm, const float* __restrict__ hop_wm,
                        const float* __restrict__ init_h, const float* __restrict__ init_c,
                        const float* __restrict__ init_i) {
    int idx = blockIdx.x * blockDim.x + threadIdx.x;
    int stride = gridDim.x * blockDim.x;
    for (int i = idx; i < 512 * 512; i += stride) {
        int n = i >> 9, k = i & 511;
        g_wqT_attn[i] = attn_wq[k * 512 + n];
        g_wqT_hop[i]  = hop_wq[k * 512 + n];
    }
    for (int i = idx; i < 1024 * 512; i += stride) {
        int n = i >> 9, k = i & 511;
        float v = (n < 512) ? attn_wm[k * 512 + n] : hop_wm[k * 512 + (n - 512)];
        __nv_bfloat16 hi = __float2bfloat16(v);
        g_BtHi[i] = hi;
        g_BtLo[i] = __float2bfloat16(v - __bfloat162float(hi));
    }
    for (int i = idx; i < NROWS; i += stride) g_sel[i] = 0;
    if (idx < 512) {
        g_h[idx] = init_h[idx];
        g_c[0][idx] = init_c[idx];
        g_x[idx] = init_i[idx];
    }
    if (idx == 0) {
        g_hopmax = 0u; g_scoremax = 0u; g_argmax = 0ull; g_done = 0;
    }
}

// ------------------------------------------------------------------
// bf16x3 split GEMM: feat[50001,1024] = [mem|stop] @ [attn_wm|hop_wm]
// BM=128 BN=128 BK=32, 256 threads, 8 warps (4m x 2n), warp tile 32x64
// ------------------------------------------------------------------
#define SA 40  // smem row stride in bf16 elems (32 + 8 pad)

__global__ __launch_bounds__(256) void kg_gemm(const float* __restrict__ attn_mem,
                                               const float* __restrict__ stop) {
    __shared__ __align__(16) __nv_bfloat16 AsHi[128 * SA];
    __shared__ __align__(16) __nv_bfloat16 AsLo[128 * SA];
    __shared__ __align__(16) __nv_bfloat16 BsHi[128 * SA];
    __shared__ __align__(16) __nv_bfloat16 BsLo[128 * SA];

    int tid = threadIdx.x, lane = tid & 31, wid = tid >> 5;
    int bn = blockIdx.x;               // 0..7
    int bm = blockIdx.y * 128;
    int wm = (wid & 3) * 32;
    int wn = (wid >> 2) * 64;

    float acc[2][8][4];
    #pragma unroll
    for (int i = 0; i < 2; i++)
        #pragma unroll
        for (int j = 0; j < 8; j++)
            #pragma unroll
            for (int k = 0; k < 4; k++) acc[i][j][k] = 0.0f;

    for (int k0 = 0; k0 < 512; k0 += 32) {
        // A tile 128x32 fp32 -> hi/lo bf16
        #pragma unroll
        for (int i = 0; i < 4; i++) {
            int idx = tid + 256 * i;
            int r = idx >> 3, c4 = (idx & 7) * 4;
            int gr = bm + r;
            float4 v;
            if (gr < STOPIDX)       v = *(const float4*)(attn_mem + (size_t)gr * 512 + k0 + c4);
            else if (gr == STOPIDX) v = *(const float4*)(stop + k0 + c4);
            else                    v = make_float4(0.f, 0.f, 0.f, 0.f);
            int off = r * SA + c4;
            float vv[4] = {v.x, v.y, v.z, v.w};
            #pragma unroll
            for (int q = 0; q < 4; q++) {
                __nv_bfloat16 hi = __float2bfloat16(vv[q]);
                AsHi[off + q] = hi;
                AsLo[off + q] = __float2bfloat16(vv[q] - __bfloat162float(hi));
            }
        }
        // B tile 128(n) x 32(k) from precomputed split-transposed weights
        #pragma unroll
        for (int i = 0; i < 2; i++) {
            int idx = tid + 256 * i;
            int r = idx >> 2, c8 = (idx & 3) * 8;
            size_t src = (size_t)(bn * 128 + r) * 512 + k0 + c8;
            *(uint4*)&BsHi[r * SA + c8] = *(const uint4*)&g_BtHi[src];
            *(uint4*)&BsLo[r * SA + c8] = *(const uint4*)&g_BtLo[src];
        }
        __syncthreads();

        #pragma unroll
        for (int kk = 0; kk < 32; kk += 16) {
            unsigned ah[2][4], al[2][4], bh[8][2], bl[8][2];
            int c = kk + 2 * (lane & 3);
            #pragma unroll
            for (int im = 0; im < 2; im++) {
                int r = wm + im * 16 + (lane >> 2);
                ah[im][0] = *(const unsigned*)&AsHi[r * SA + c];
                ah[im][1] = *(const unsigned*)&AsHi[(r + 8) * SA + c];
                ah[im][2] = *(const unsigned*)&AsHi[r * SA + c + 8];
                ah[im][3] = *(const unsigned*)&AsHi[(r + 8) * SA + c + 8];
                al[im][0] = *(const unsigned*)&AsLo[r * SA + c];
                al[im][1] = *(const unsigned*)&AsLo[(r + 8) * SA + c];
                al[im][2] = *(const unsigned*)&AsLo[r * SA + c + 8];
                al[im][3] = *(const unsigned*)&AsLo[(r + 8) * SA + c + 8];
            }
            #pragma unroll
            for (int in_ = 0; in_ < 8; in_++) {
                int n = wn + in_ * 8 + (lane >> 2);
                bh[in_][0] = *(const unsigned*)&BsHi[n * SA + c];
                bh[in_][1] = *(const unsigned*)&BsHi[n * SA + c + 8];
                bl[in_][0] = *(const unsigned*)&BsLo[n * SA + c];
                bl[in_][1] = *(const unsigned*)&BsLo[n * SA + c + 8];
            }
            #pragma unroll
            for (int im = 0; im < 2; im++)
                #pragma unroll
                for (int in_ = 0; in_ < 8; in_++) {
                    mma_bf16(acc[im][in_], ah[im], bh[in_]);
                    mma_bf16(acc[im][in_], ah[im], bl[in_]);
                    mma_bf16(acc[im][in_], al[im], bh[in_]);
                }
        }
        __syncthreads();
    }

    float* dst = (bn < 4) ? g_feat_a : g_feat_h;
    int cbase = (bn & 3) * 128 + wn;
    #pragma unroll
    for (int im = 0; im < 2; im++) {
        int r0 = bm + wm + im * 16 + (lane >> 2);
        #pragma unroll
        for (int in_ = 0; in_ < 8; in_++) {
            int cl = cbase + in_ * 8 + 2 * (lane & 3);
            if (r0 < NROWS)
                *(float2*)&dst[(size_t)r0 * 512 + cl] = make_float2(acc[im][in_][0], acc[im][in_][1]);
            if (r0 + 8 < NROWS)
                *(float2*)&dst[(size_t)(r0 + 8) * 512 + cl] = make_float2(acc[im][in_][2], acc[im][in_][3]);
        }
    }
}

// ------------------------------------------------------------------
// LSTM gates: gates[r] = w_ih[r]·x + w_hh[r]·h + b_ih[r] + b_hh[r]
// 64 blocks x 256: warp per row, 4 rows per warp
// ------------------------------------------------------------------
__global__ __launch_bounds__(256) void kg_gates(const float* __restrict__ w_ih,
                                                const float* __restrict__ w_hh,
                                                const float* __restrict__ b_ih,
                                                const float* __restrict__ b_hh) {
    __shared__ __align__(16) float sx[512];
    __shared__ __align__(16) float sh[512];
    int tid = threadIdx.x, lane = tid & 31, w = tid >> 5;
    sx[tid] = g_x[tid]; sx[tid + 256] = g_x[tid + 256];
    sh[tid] = g_h[tid]; sh[tid + 256] = g_h[tid + 256];
    __syncthreads();
    const float4* xv = (const float4*)sx;
    const float4* hv = (const float4*)sh;
    #pragma unroll
    for (int rr = 0; rr < 4; rr++) {
        int r = blockIdx.x * 32 + rr * 8 + w;
        const float4* wi = (const float4*)(w_ih + (size_t)r * 512);
        const float4* wh = (const float4*)(w_hh + (size_t)r * 512);
        float s = 0.f;
        #pragma unroll
        for (int j = 0; j < 4; j++) {
            float4 a = wi[lane + 32 * j], b = xv[lane + 32 * j];
            s += a.x * b.x + a.y * b.y + a.z * b.z + a.w * b.w;
            float4 c = wh[lane + 32 * j], d = hv[lane + 32 * j];
            s += c.x * d.x + c.y * d.y + c.z * d.z + c.w * d.w;
        }
        s = warp_sum(s);
        if (lane == 0) g_gates[r] = s + b_ih[r] + b_hh[r];
    }
}

// ------------------------------------------------------------------
// h,c from gates (block 0 commits), then qw = h @ hop_wq
// 64 blocks x 256: each block recomputes h, does 8 warp-dot outputs
// ------------------------------------------------------------------
__global__ __launch_bounds__(256) void kg_hcqw(int par) {
    __shared__ __align__(16) float sh[512];
    int tid = threadIdx.x, lane = tid & 31, w = tid >> 5;
    #pragma unroll
    for (int rep = 0; rep < 2; rep++) {
        int e = tid + rep * 256;
        float gi = g_gates[e], gf = g_gates[512 + e];
        float gg = g_gates[1024 + e], go = g_gates[1536 + e];
        float c = fast_sig(gf) * g_c[par][e] + fast_sig(gi) * fast_tanh(gg);
        float h = fast_sig(go) * fast_tanh(c);
        sh[e] = h;
        if (blockIdx.x == 0) { g_c[par ^ 1][e] = c; g_h[e] = h; }
    }
    __syncthreads();
    int n = blockIdx.x * 8 + w;
    const float4* W = (const float4*)(g_wqT_hop + (size_t)n * 512);
    const float4* hv = (const float4*)sh;
    float s = 0.f;
    #pragma unroll
    for (int j = 0; j < 4; j++) {
        float4 a = W[lane + 32 * j], b = hv[lane + 32 * j];
        s += a.x * b.x + a.y * b.y + a.z * b.z + a.w * b.w;
    }
    s = warp_sum(s);
    if (lane == 0) g_qw[n] = s;
}

// ------------------------------------------------------------------
// Hop glimpse pass: flash-style online softmax over hop_feat rows
// s_m = tanh(hop_feat[m] + qw) · hop_v;  partial (mu, sum, vec) per block
// ------------------------------------------------------------------
__global__ __launch_bounds__(256) void kg_hop(const float* __restrict__ hop_v) {
    __shared__ __align__(16) float s_qw[512];
    __shared__ __align__(16) float s_wvec[8][512];
    __shared__ float s_mu[8], s_sum[8];
    int tid = threadIdx.x, lane = tid & 31, w = tid >> 5;
    s_qw[tid] = g_qw[tid]; s_qw[tid + 256] = g_qw[tid + 256];
    __syncthreads();
    float4 q4[4], v4[4];
    #pragma unroll
    for (int j = 0; j < 4; j++) {
        q4[j] = ((const float4*)s_qw)[lane + 32 * j];
        v4[j] = ((const float4*)hop_v)[lane + 32 * j];
    }
    const int chunk = (NROWS + PB - 1) / PB;
    int base = blockIdx.x * chunk;
    int end = min(base + chunk, NROWS);
    float mu = -INFINITY, ssum = 0.f;
    float4 acc[4];
    #pragma unroll
    for (int j = 0; j < 4; j++) acc[j] = make_float4(0.f, 0.f, 0.f, 0.f);

    for (int m = base + w; m < end; m += 8) {
        const float4* row = (const float4*)(g_feat_h + (size_t)m * 512);
        float4 f[4];
        float sp = 0.f;
        #pragma unroll
        for (int j = 0; j < 4; j++) {
            f[j] = row[lane + 32 * j];
            sp += dot_tanh4(f[j], q4[j], v4[j]);
        }
        float s = warp_sum(sp);
        float mn = fmaxf(mu, s);
        float al = __expf(mu - mn);
        float wg = __expf(s - mn);
        ssum = ssum * al + wg;
        #pragma unroll
        for (int j = 0; j < 4; j++) {
            acc[j].x = acc[j].x * al + wg * f[j].x;
            acc[j].y = acc[j].y * al + wg * f[j].y;
            acc[j].z = acc[j].z * al + wg * f[j].z;
            acc[j].w = acc[j].w * al + wg * f[j].w;
        }
        mu = mn;
    }
    if (lane == 0) { s_mu[w] = mu; s_sum[w] = ssum; }
    __syncthreads();
    float bmu = s_mu[0];
    #pragma unroll
    for (int i = 1; i < 8; i++) bmu = fmaxf(bmu, s_mu[i]);
    float sc = (mu > -3.0e38f) ? __expf(mu - bmu) : 0.f;
    #pragma unroll
    for (int j = 0; j < 4; j++) {
        float4 a = acc[j];
        a.x *= sc; a.y *= sc; a.z *= sc; a.w *= sc;
        ((float4*)s_wvec[w])[lane + 32 * j] = a;
    }
    __syncthreads();
    float v1 = 0.f, v2 = 0.f;
    #pragma unroll
    for (int i = 0; i < 8; i++) { v1 += s_wvec[i][tid]; v2 += s_wvec[i][tid + 256]; }
    g_pvec[blockIdx.x * 512 + tid] = v1;
    g_pvec[blockIdx.x * 512 + tid + 256] = v2;
    if (tid == 0) {
        float bs = 0.f;
        #pragma unroll
        for (int i = 0; i < 8; i++)
            if (s_mu[i] > -3.0e38f) bs += s_sum[i] * __expf(s_mu[i] - bmu);
        g_pmu[blockIdx.x] = bmu;
        g_psum[blockIdx.x] = bs;
        atomicMax(&g_hopmax, ford(bmu));
    }
}

// ------------------------------------------------------------------
// Combine hop partials -> q2, then qw2 = q2 @ attn_wq. Single block x512.
// ------------------------------------------------------------------
__global__ __launch_bounds__(512) void kg_combine() {
    __shared__ float se[PB];
    __shared__ __align__(16) float sred4[4][512];
    __shared__ __align__(16) float s_q2[512];
    __shared__ float red[32];
    int tid = threadIdx.x, lane = tid & 31, w = tid >> 5;
    float mu = funord(g_hopmax);
    for (int b = tid; b < PB; b += 512) {
        float pm = g_pmu[b];
        se[b] = (pm > -3.0e38f) ? __expf(pm - mu) : 0.f;
    }
    __syncthreads();
    float ps = 0.f;
    for (int b = tid; b < PB; b += 512) ps += g_psum[b] * se[b];
    ps = warp_sum(ps);
    if (lane == 0) red[w] = ps;
    __syncthreads();
    if (tid < 32) {
        float r = (tid < 16) ? red[tid] : 0.f;
        r = warp_sum(r);
        if (tid == 0) red[0] = r;
    }
    __syncthreads();
    float S = red[0];
    int grp = tid >> 7, l = tid & 127;
    float4 a = make_float4(0.f, 0.f, 0.f, 0.f);
    for (int b = grp; b < PB; b += 4) {
        float e = se[b];
        float4 v = *(const float4*)&g_pvec[b * 512 + 4 * l];
        a.x += e * v.x; a.y += e * v.y; a.z += e * v.z; a.w += e * v.w;
    }
    *(float4*)&sred4[grp][4 * l] = a;
    __syncthreads();
    s_q2[tid] = (sred4[0][tid] + sred4[1][tid] + sred4[2][tid] + sred4[3][tid]) / S;
    __syncthreads();
    const float4* q4p = (const float4*)s_q2;
    for (int i = 0; i < 32; i++) {
        int n = w * 32 + i;
        const float4* Wp = (const float4*)(g_wqT_attn + (size_t)n * 512);
        float s = 0.f;
        #pragma unroll
        for (int j = 0; j < 4; j++) {
            float4 aa = Wp[lane + 32 * j], bb = q4p[lane + 32 * j];
            s += aa.x * bb.x + aa.y * bb.y + aa.z * bb.z + aa.w * bb.w;
        }
        s = warp_sum(s);
        if (lane == 0) g_qw2[n] = s;
    }
    if (tid == 0) g_hopmax = 0u;
}

// ------------------------------------------------------------------
// Attention score pass: masked scores, partial (mu,sum), packed argmax(score+g)
// ------------------------------------------------------------------
__global__ __launch_bounds__(256) void kg_score(const float* __restrict__ attn_v,
                                                const float* __restrict__ grow) {
    __shared__ __align__(16) float s_qw[512];
    __shared__ float s_mu[8], s_sum[8];
    __shared__ unsigned long long s_key[8];
    int tid = threadIdx.x, lane = tid & 31, w = tid >> 5;
    s_qw[tid] = g_qw2[tid]; s_qw[tid + 256] = g_qw2[tid + 256];
    __syncthreads();
    float4 q4[4], v4[4];
    #pragma unroll
    for (int j = 0; j < 4; j++) {
        q4[j] = ((const float4*)s_qw)[lane + 32 * j];
        v4[j] = ((const float4*)attn_v)[lane + 32 * j];
    }
    const int chunk = (NROWS + PB - 1) / PB;
    int base = blockIdx.x * chunk;
    int end = min(base + chunk, NROWS);
    float mu = -INFINITY, ssum = 0.f;
    unsigned long long key = 0ull;
    for (int m = base + w; m < end; m += 8) {
        const float4* row = (const float4*)(g_feat_a + (size_t)m * 512);
        float sp = 0.f;
        #pragma unroll
        for (int j = 0; j < 4; j++) {
            float4 f = row[lane + 32 * j];
            sp += dot_tanh4(f, q4[j], v4[j]);
        }
        float s = warp_sum(sp);
        if (g_sel[m]) s = NEGF;
        float mn = fmaxf(mu, s);
        ssum = ssum * __expf(mu - mn) + __expf(s - mn);
        mu = mn;
        if (lane == 0) {
            float gg = grow[m];
            unsigned long long k = ((unsigned long long)ford(s + gg) << 32) |
                                   (unsigned)(NROWS - m);
            if (k > key) key = k;
        }
    }
    if (lane == 0) { s_mu[w] = mu; s_sum[w] = ssum; s_key[w] = key; }
    __syncthreads();
    if (tid == 0) {
        float bmu = s_mu[0];
        #pragma unroll
        for (int i = 1; i < 8; i++) bmu = fmaxf(bmu, s_mu[i]);
        float bs = 0.f;
        unsigned long long bk = 0ull;
        #pragma unroll
        for (int i = 0; i < 8; i++) {
            if (s_mu[i] > -3.0e38f) bs += s_sum[i] * __expf(s_mu[i] - bmu);
            if (s_key[i] > bk) bk = s_key[i];
        }
        g_pmu[blockIdx.x] = bmu;
        g_psum[blockIdx.x] = bs;
        atomicMax(&g_scoremax, ford(bmu));
        if (bk) atomicMax(&g_argmax, bk);
    }
}

// ------------------------------------------------------------------
// Finalize step: logsumexp, logp, done/sel/x updates, outputs
// ------------------------------------------------------------------
__global__ __launch_bounds__(512) void kg_final(int t, const float* __restrict__ attn_mem,
                                                const float* __restrict__ attn_v,
                                                float* __restrict__ out) {
    __shared__ float red[32];
    __shared__ float bc[2];
    int tid = threadIdx.x, lane = tid & 31, w = tid >> 5;
    int done_prev = g_done;
    unsigned long long key = g_argmax;
    int out_idx = NROWS - (int)(unsigned)(key & 0xFFFFFFFFull);
    float mu = funord(g_scoremax);
    float ps = 0.f;
    for (int b = tid; b < PB; b += 512) {
        float pm = g_pmu[b];
        if (pm > -3.0e38f) ps += g_psum[b] * __expf(pm - mu);
    }
    float sc = fast_tanh(g_feat_a[(size_t)out_idx * 512 + tid] + g_qw2[tid]) * attn_v[tid];
    ps = warp_sum(ps);
    sc = warp_sum(sc);
    if (lane == 0) red[w] = ps;
    __syncthreads();
    if (tid < 32) {
        float r = (tid < 16) ? red[tid] : 0.f;
        r = warp_sum(r);
        if (tid == 0) bc[0] = r;
    }
    __syncthreads();
    if (lane == 0) red[w] = sc;
    __syncthreads();
    if (tid < 32) {
        float r = (tid < 16) ? red[tid] : 0.f;
        r = warp_sum(r);
        if (tid == 0) bc[1] = r;
    }
    __syncthreads();
    float Ssum = bc[0], score_out = bc[1];
    int new_done = done_prev | (out_idx == STOPIDX);
    if (!new_done) g_x[tid] = attn_mem[(size_t)out_idx * 512 + tid];
    if (tid == 0) {
        float logp = score_out - mu - __logf(Ssum);
        out[t] = (float)(done_prev ? STOPIDX : out_idx);
        out[TSTEPS + t] = done_prev ? 0.f : logp;
        if (!done_prev) g_sel[out_idx] = 1;
        g_done = new_done;
        g_scoremax = 0u;
        g_argmax = 0ull;
    }
}

// ------------------------------------------------------------------
// Launch
// ------------------------------------------------------------------
extern "C" void kernel_launch(void* const* d_in, const int* in_sizes, int n_in,
                              void* d_out, int out_size) {
    const float* attn_mem = (const float*)d_in[0];
    const float* stop     = (const float*)d_in[1];
    const float* init_h   = (const float*)d_in[2];
    const float* init_c   = (const float*)d_in[3];
    const float* init_i   = (const float*)d_in[4];
    const float* attn_wm  = (const float*)d_in[5];
    const float* attn_wq  = (const float*)d_in[6];
    const float* attn_v   = (const float*)d_in[7];
    const float* hop_wm   = (const float*)d_in[8];
    const float* hop_wq   = (const float*)d_in[9];
    const float* hop_v    = (const float*)d_in[10];
    const float* w_ih     = (const float*)d_in[11];
    const float* w_hh     = (const float*)d_in[12];
    const float* b_ih     = (const float*)d_in[13];
    const float* b_hh     = (const float*)d_in[14];
    const float* gumbel   = (const float*)d_in[15];
    float* out = (float*)d_out;

    kg_init<<<512, 256>>>(attn_wq, hop_wq, attn_wm, hop_wm, init_h, init_c, init_i);
    kg_gemm<<<dim3(8, (NROWS + 127) / 128), 256>>>(attn_mem, stop);
    for (int t = 0; t < TSTEPS; t++) {
        kg_gates<<<64, 256>>>(w_ih, w_hh, b_ih, b_hh);
        kg_hcqw<<<64, 256>>>(t & 1);
        kg_hop<<<PB, 256>>>(hop_v);
        kg_combine<<<1, 512>>>();
        kg_score<<<PB, 256>>>(attn_v, gumbel + (size_t)t * NROWS);
        kg_final<<<1, 512>>>(t, attn_mem, attn_v, out);
    }
}

// round 5
// speedup vs baseline: 1.7012x; 1.7012x over previous
#include <cuda_runtime.h>
#include <cuda_bf16.h>
#include <cstdint>
#include <math.h>

#define NROWS 50001
#define NPAD 50048          // 391*128
#define STOPIDX 50000
#define NEGF (-1e18f)
#define TSTEPS 16
#define PB 592

// ==================================================================
// Static device state
// ==================================================================
__device__ __align__(16) float g_feat_a[(size_t)NROWS * 512];
__device__ __align__(16) float g_feat_h[(size_t)NROWS * 512];
__device__ __align__(16) __nv_bfloat16 g_AHi[(size_t)NPAD * 512];
__device__ __align__(16) __nv_bfloat16 g_ALo[(size_t)NPAD * 512];
__device__ __align__(16) __nv_bfloat16 g_BtHi[1024 * 512];
__device__ __align__(16) __nv_bfloat16 g_BtLo[1024 * 512];
__device__ __align__(16) float g_wqT_attn[512 * 512];
__device__ __align__(16) float g_wqT_hop[512 * 512];
__device__ __align__(16) float g_h[512];
__device__ __align__(16) float g_c[2][512];
__device__ __align__(16) float g_x[512];
__device__ __align__(16) float g_gates[2048];
__device__ __align__(16) float g_qw[512];
__device__ __align__(16) float g_qw2[512];
__device__ __align__(16) float g_q2num[512];
__device__ float g_q2den;
__device__ float g_S;
__device__ unsigned char g_sel[NROWS];
__device__ unsigned long long g_argmax;
__device__ int g_done;

// ==================================================================
// Helpers
// ==================================================================
__device__ __forceinline__ unsigned ford(float f) {
    unsigned u = __float_as_uint(f);
    return (u & 0x80000000u) ? ~u : (u | 0x80000000u);
}
__device__ __forceinline__ float htanh(float x) {
    float r;
    asm("tanh.approx.f32 %0, %1;" : "=f"(r) : "f"(x));
    return r;
}
__device__ __forceinline__ float hsig(float x) {
    return 0.5f * htanh(0.5f * x) + 0.5f;
}
__device__ __forceinline__ float dot_tanh4(float4 f, float4 q, float4 v) {
    return htanh(f.x + q.x) * v.x + htanh(f.y + q.y) * v.y +
           htanh(f.z + q.z) * v.z + htanh(f.w + q.w) * v.w;
}
__device__ __forceinline__ float warp_sum(float s) {
    #pragma unroll
    for (int o = 16; o; o >>= 1) s += __shfl_xor_sync(0xFFFFFFFFu, s, o);
    return s;
}
__device__ __forceinline__ void mma_bf16(float c[4], const unsigned a[4], const unsigned b[2]) {
    asm volatile(
        "mma.sync.aligned.m16n8k16.row.col.f32.bf16.bf16.f32 "
        "{%0,%1,%2,%3},{%4,%5,%6,%7},{%8,%9},{%0,%1,%2,%3};"
        : "+f"(c[0]), "+f"(c[1]), "+f"(c[2]), "+f"(c[3])
        : "r"(a[0]), "r"(a[1]), "r"(a[2]), "r"(a[3]), "r"(b[0]), "r"(b[1]));
}

// ==================================================================
// Init: weight transposes + bf16 hi/lo splits + state
// ==================================================================
__global__ void kg_init(const float* __restrict__ attn_wq, const float* __restrict__ hop_wq,
                        const float* __restrict__ attn_wm, const float* __restrict__ hop_wm,
                        const float* __restrict__ attn_mem, const float* __restrict__ stop,
                        const float* __restrict__ init_h, const float* __restrict__ init_c,
                        const float* __restrict__ init_i) {
    int idx = blockIdx.x * blockDim.x + threadIdx.x;
    int stride = gridDim.x * blockDim.x;
    for (int i = idx; i < 512 * 512; i += stride) {
        int n = i >> 9, k = i & 511;
        g_wqT_attn[i] = attn_wq[k * 512 + n];
        g_wqT_hop[i]  = hop_wq[k * 512 + n];
    }
    for (int i = idx; i < 1024 * 512; i += stride) {
        int n = i >> 9, k = i & 511;
        float v = (n < 512) ? attn_wm[k * 512 + n] : hop_wm[k * 512 + (n - 512)];
        __nv_bfloat16 hi = __float2bfloat16(v);
        g_BtHi[i] = hi;
        g_BtLo[i] = __float2bfloat16(v - __bfloat162float(hi));
    }
    for (size_t i = idx; i < (size_t)NPAD * 512; i += stride) {
        int r = (int)(i >> 9);
        float v;
        if (r < STOPIDX) v = attn_mem[i];
        else if (r == STOPIDX) v = stop[i & 511];
        else v = 0.0f;
        __nv_bfloat16 hi = __float2bfloat16(v);
        g_AHi[i] = hi;
        g_ALo[i] = __float2bfloat16(v - __bfloat162float(hi));
    }
    for (int i = idx; i < NROWS; i += stride) g_sel[i] = 0;
    if (idx < 512) {
        g_h[idx] = init_h[idx];
        g_c[0][idx] = init_c[idx];
        g_x[idx] = init_i[idx];
    }
    if (idx == 0) { g_argmax = 0ull; g_done = 0; }
}

// ==================================================================
// bf16x3 split GEMM (mma.sync): feat[50001,1024] = A @ [attn_wm|hop_wm]
// BM=128 BN=128 BK=32; 256 thr, 8 warps (4m x 2n), warp tile 32x64
// A/B pre-split bf16 hi/lo in gmem; register-prefetch double buffering
// ==================================================================
#define SA 40  // smem row stride in bf16 elems (32 + 8 pad); 80B pitch (16B-aligned)

__global__ __launch_bounds__(256) void kg_gemm() {
    __shared__ __align__(16) __nv_bfloat16 AsHi[128 * SA];
    __shared__ __align__(16) __nv_bfloat16 AsLo[128 * SA];
    __shared__ __align__(16) __nv_bfloat16 BsHi[128 * SA];
    __shared__ __align__(16) __nv_bfloat16 BsLo[128 * SA];

    int tid = threadIdx.x, lane = tid & 31, wid = tid >> 5;
    int bn = blockIdx.x;               // 0..7 over 1024 combined cols
    int bm = blockIdx.y * 128;
    int wm = (wid & 3) * 32;
    int wn = (wid >> 2) * 64;

    float acc[2][8][4];
    #pragma unroll
    for (int i = 0; i < 2; i++)
        #pragma unroll
        for (int j = 0; j < 8; j++)
            #pragma unroll
            for (int k = 0; k < 4; k++) acc[i][j][k] = 0.0f;

    // per-thread tile coords: 512 uint4 per (matrix,half); 2 per thread
    int r0 = tid >> 2, c80 = (tid & 3) * 8;
    int r1 = (tid + 256) >> 2, c81 = ((tid + 256) & 3) * 8;

    uint4 pAh[2], pAl[2], pBh[2], pBl[2];
    {
        size_t a0 = (size_t)(bm + r0) * 512 + c80, a1 = (size_t)(bm + r1) * 512 + c81;
        size_t b0 = (size_t)(bn * 128 + r0) * 512 + c80, b1 = (size_t)(bn * 128 + r1) * 512 + c81;
        pAh[0] = *(const uint4*)&g_AHi[a0]; pAh[1] = *(const uint4*)&g_AHi[a1];
        pAl[0] = *(const uint4*)&g_ALo[a0]; pAl[1] = *(const uint4*)&g_ALo[a1];
        pBh[0] = *(const uint4*)&g_BtHi[b0]; pBh[1] = *(const uint4*)&g_BtHi[b1];
        pBl[0] = *(const uint4*)&g_BtLo[b0]; pBl[1] = *(const uint4*)&g_BtLo[b1];
    }

    for (int k0 = 0; k0 < 512; k0 += 32) {
        // commit prefetched tile to smem
        *(uint4*)&AsHi[r0 * SA + c80] = pAh[0]; *(uint4*)&AsHi[r1 * SA + c81] = pAh[1];
        *(uint4*)&AsLo[r0 * SA + c80] = pAl[0]; *(uint4*)&AsLo[r1 * SA + c81] = pAl[1];
        *(uint4*)&BsHi[r0 * SA + c80] = pBh[0]; *(uint4*)&BsHi[r1 * SA + c81] = pBh[1];
        *(uint4*)&BsLo[r0 * SA + c80] = pBl[0]; *(uint4*)&BsLo[r1 * SA + c81] = pBl[1];
        __syncthreads();

        if (k0 < 480) {  // prefetch next stage
            int kn = k0 + 32;
            size_t a0 = (size_t)(bm + r0) * 512 + kn + c80, a1 = (size_t)(bm + r1) * 512 + kn + c81;
            size_t b0 = (size_t)(bn * 128 + r0) * 512 + kn + c80, b1 = (size_t)(bn * 128 + r1) * 512 + kn + c81;
            pAh[0] = *(const uint4*)&g_AHi[a0]; pAh[1] = *(const uint4*)&g_AHi[a1];
            pAl[0] = *(const uint4*)&g_ALo[a0]; pAl[1] = *(const uint4*)&g_ALo[a1];
            pBh[0] = *(const uint4*)&g_BtHi[b0]; pBh[1] = *(const uint4*)&g_BtHi[b1];
            pBl[0] = *(const uint4*)&g_BtLo[b0]; pBl[1] = *(const uint4*)&g_BtLo[b1];
        }

        #pragma unroll
        for (int kk = 0; kk < 32; kk += 16) {
            unsigned ah[2][4], al[2][4], bh[8][2], bl[8][2];
            int c = kk + 2 * (lane & 3);
            #pragma unroll
            for (int im = 0; im < 2; im++) {
                int r = wm + im * 16 + (lane >> 2);
                ah[im][0] = *(const unsigned*)&AsHi[r * SA + c];
                ah[im][1] = *(const unsigned*)&AsHi[(r + 8) * SA + c];
                ah[im][2] = *(const unsigned*)&AsHi[r * SA + c + 8];
                ah[im][3] = *(const unsigned*)&AsHi[(r + 8) * SA + c + 8];
                al[im][0] = *(const unsigned*)&AsLo[r * SA + c];
                al[im][1] = *(const unsigned*)&AsLo[(r + 8) * SA + c];
                al[im][2] = *(const unsigned*)&AsLo[r * SA + c + 8];
                al[im][3] = *(const unsigned*)&AsLo[(r + 8) * SA + c + 8];
            }
            #pragma unroll
            for (int in_ = 0; in_ < 8; in_++) {
                int n = wn + in_ * 8 + (lane >> 2);
                bh[in_][0] = *(const unsigned*)&BsHi[n * SA + c];
                bh[in_][1] = *(const unsigned*)&BsHi[n * SA + c + 8];
                bl[in_][0] = *(const unsigned*)&BsLo[n * SA + c];
                bl[in_][1] = *(const unsigned*)&BsLo[n * SA + c + 8];
            }
            #pragma unroll
            for (int im = 0; im < 2; im++)
                #pragma unroll
                for (int in_ = 0; in_ < 8; in_++) {
                    mma_bf16(acc[im][in_], ah[im], bh[in_]);
                    mma_bf16(acc[im][in_], ah[im], bl[in_]);
                    mma_bf16(acc[im][in_], al[im], bh[in_]);
                }
        }
        __syncthreads();
    }

    float* dst = (bn < 4) ? g_feat_a : g_feat_h;
    int cbase = (bn & 3) * 128 + wn;
    #pragma unroll
    for (int im = 0; im < 2; im++) {
        int rr = bm + wm + im * 16 + (lane >> 2);
        #pragma unroll
        for (int in_ = 0; in_ < 8; in_++) {
            int cl = cbase + in_ * 8 + 2 * (lane & 3);
            if (rr < NROWS)
                *(float2*)&dst[(size_t)rr * 512 + cl] = make_float2(acc[im][in_][0], acc[im][in_][1]);
            if (rr + 8 < NROWS)
                *(float2*)&dst[(size_t)(rr + 8) * 512 + cl] = make_float2(acc[im][in_][2], acc[im][in_][3]);
        }
    }
}

// ==================================================================
// LSTM gates
// ==================================================================
__global__ __launch_bounds__(256) void kg_gates(const float* __restrict__ w_ih,
                                                const float* __restrict__ w_hh,
                                                const float* __restrict__ b_ih,
                                                const float* __restrict__ b_hh) {
    __shared__ __align__(16) float sx[512];
    __shared__ __align__(16) float sh[512];
    int tid = threadIdx.x, lane = tid & 31, w = tid >> 5;
    sx[tid] = g_x[tid]; sx[tid + 256] = g_x[tid + 256];
    sh[tid] = g_h[tid]; sh[tid + 256] = g_h[tid + 256];
    __syncthreads();
    const float4* xv = (const float4*)sx;
    const float4* hv = (const float4*)sh;
    #pragma unroll
    for (int rr = 0; rr < 4; rr++) {
        int r = blockIdx.x * 32 + rr * 8 + w;
        const float4* wi = (const float4*)(w_ih + (size_t)r * 512);
        const float4* wh = (const float4*)(w_hh + (size_t)r * 512);
        float s = 0.f;
        #pragma unroll
        for (int j = 0; j < 4; j++) {
            float4 a = wi[lane + 32 * j], b = xv[lane + 32 * j];
            s += a.x * b.x + a.y * b.y + a.z * b.z + a.w * b.w;
            float4 c = wh[lane + 32 * j], d = hv[lane + 32 * j];
            s += c.x * d.x + c.y * d.y + c.z * d.z + c.w * d.w;
        }
        s = warp_sum(s);
        if (lane == 0) g_gates[r] = s + b_ih[r] + b_hh[r];
    }
}

// ==================================================================
// h,c update + qw = h @ hop_wq; block 0 zeros hop accumulators
// ==================================================================
__global__ __launch_bounds__(256) void kg_hcqw(int par) {
    __shared__ __align__(16) float sh[512];
    int tid = threadIdx.x, lane = tid & 31, w = tid >> 5;
    if (blockIdx.x == 0) {
        g_q2num[tid] = 0.f; g_q2num[tid + 256] = 0.f;
        if (tid == 0) g_q2den = 0.f;
    }
    #pragma unroll
    for (int rep = 0; rep < 2; rep++) {
        int e = tid + rep * 256;
        float gi = g_gates[e], gf = g_gates[512 + e];
        float gg = g_gates[1024 + e], go = g_gates[1536 + e];
        float c = hsig(gf) * g_c[par][e] + hsig(gi) * htanh(gg);
        float h = hsig(go) * htanh(c);
        sh[e] = h;
        if (blockIdx.x == 0) { g_c[par ^ 1][e] = c; g_h[e] = h; }
    }
    __syncthreads();
    int n = blockIdx.x * 8 + w;
    const float4* W = (const float4*)(g_wqT_hop + (size_t)n * 512);
    const float4* hv = (const float4*)sh;
    float s = 0.f;
    #pragma unroll
    for (int j = 0; j < 4; j++) {
        float4 a = W[lane + 32 * j], b = hv[lane + 32 * j];
        s += a.x * b.x + a.y * b.y + a.z * b.z + a.w * b.w;
    }
    s = warp_sum(s);
    if (lane == 0) g_qw[n] = s;
}

// ==================================================================
// Hop glimpse pass: no-max softmax (scores bounded), atomicAdd partials
// ==================================================================
__global__ __launch_bounds__(256) void kg_hop(const float* __restrict__ hop_v) {
    __shared__ __align__(16) float s_qw[512];
    __shared__ __align__(16) float s_wvec[8][512];
    __shared__ float s_den[8];
    int tid = threadIdx.x, lane = tid & 31, w = tid >> 5;
    s_qw[tid] = g_qw[tid]; s_qw[tid + 256] = g_qw[tid + 256];
    __syncthreads();
    float4 q4[4], v4[4];
    #pragma unroll
    for (int j = 0; j < 4; j++) {
        q4[j] = ((const float4*)s_qw)[lane + 32 * j];
        v4[j] = ((const float4*)hop_v)[lane + 32 * j];
    }
    const int chunk = (NROWS + PB - 1) / PB;
    int base = blockIdx.x * chunk;
    int end = min(base + chunk, NROWS);
    float den = 0.f;
    float4 acc[4];
    #pragma unroll
    for (int j = 0; j < 4; j++) acc[j] = make_float4(0.f, 0.f, 0.f, 0.f);

    for (int m = base + w; m < end; m += 8) {
        const float4* row = (const float4*)(g_feat_h + (size_t)m * 512);
        float4 f[4];
        float sp = 0.f;
        #pragma unroll
        for (int j = 0; j < 4; j++) {
            f[j] = row[lane + 32 * j];
            sp += dot_tanh4(f[j], q4[j], v4[j]);
        }
        float s = warp_sum(sp);
        float wg = __expf(s);
        den += wg;
        #pragma unroll
        for (int j = 0; j < 4; j++) {
            acc[j].x += wg * f[j].x; acc[j].y += wg * f[j].y;
            acc[j].z += wg * f[j].z; acc[j].w += wg * f[j].w;
        }
    }
    #pragma unroll
    for (int j = 0; j < 4; j++) ((float4*)s_wvec[w])[lane + 32 * j] = acc[j];
    if (lane == 0) s_den[w] = den;
    __syncthreads();
    float v1 = 0.f, v2 = 0.f;
    #pragma unroll
    for (int i = 0; i < 8; i++) { v1 += s_wvec[i][tid]; v2 += s_wvec[i][tid + 256]; }
    atomicAdd(&g_q2num[tid], v1);
    atomicAdd(&g_q2num[tid + 256], v2);
    if (tid == 0) {
        float d = 0.f;
        #pragma unroll
        for (int i = 0; i < 8; i++) d += s_den[i];
        if (d != 0.f) atomicAdd(&g_q2den, d);
    }
}

// ==================================================================
// q2 = num/den; qw2 = q2 @ attn_wq; zeros g_S
// ==================================================================
__global__ __launch_bounds__(256) void kg_qw2() {
    __shared__ __align__(16) float sq[512];
    int tid = threadIdx.x, lane = tid & 31, w = tid >> 5;
    float den = g_q2den;
    sq[tid] = g_q2num[tid] / den;
    sq[tid + 256] = g_q2num[tid + 256] / den;
    if (blockIdx.x == 0 && tid == 0) g_S = 0.f;
    __syncthreads();
    int n = blockIdx.x * 8 + w;
    const float4* W = (const float4*)(g_wqT_attn + (size_t)n * 512);
    const float4* qv = (const float4*)sq;
    float s = 0.f;
    #pragma unroll
    for (int j = 0; j < 4; j++) {
        float4 a = W[lane + 32 * j], b = qv[lane + 32 * j];
        s += a.x * b.x + a.y * b.y + a.z * b.z + a.w * b.w;
    }
    s = warp_sum(s);
    if (lane == 0) g_qw2[n] = s;
}

// ==================================================================
// Score pass: sum(exp(s)) + packed argmax(score + gumbel)
// ==================================================================
__global__ __launch_bounds__(256) void kg_score(const float* __restrict__ attn_v,
                                                const float* __restrict__ grow) {
    __shared__ __align__(16) float s_qw[512];
    __shared__ float s_den[8];
    __shared__ unsigned long long s_key[8];
    int tid = threadIdx.x, lane = tid & 31, w = tid >> 5;
    s_qw[tid] = g_qw2[tid]; s_qw[tid + 256] = g_qw2[tid + 256];
    __syncthreads();
    float4 q4[4], v4[4];
    #pragma unroll
    for (int j = 0; j < 4; j++) {
        q4[j] = ((const float4*)s_qw)[lane + 32 * j];
        v4[j] = ((const float4*)attn_v)[lane + 32 * j];
    }
    const int chunk = (NROWS + PB - 1) / PB;
    int base = blockIdx.x * chunk;
    int end = min(base + chunk, NROWS);
    float ssum = 0.f;
    unsigned long long key = 0ull;
    for (int m = base + w; m < end; m += 8) {
        const float4* row = (const float4*)(g_feat_a + (size_t)m * 512);
        float sp = 0.f;
        #pragma unroll
        for (int j = 0; j < 4; j++) {
            float4 f = row[lane + 32 * j];
            sp += dot_tanh4(f, q4[j], v4[j]);
        }
        float s = warp_sum(sp);
        if (g_sel[m]) s = NEGF;
        ssum += __expf(s);
        if (lane == 0) {
            unsigned long long k = ((unsigned long long)ford(s + grow[m]) << 32) |
                                   (unsigned)(NROWS - m);
            if (k > key) key = k;
        }
    }
    if (lane == 0) { s_den[w] = ssum; s_key[w] = key; }
    __syncthreads();
    if (tid == 0) {
        float bs = 0.f;
        unsigned long long bk = 0ull;
        #pragma unroll
        for (int i = 0; i < 8; i++) {
            bs += s_den[i];
            if (s_key[i] > bk) bk = s_key[i];
        }
        if (bs != 0.f) atomicAdd(&g_S, bs);
        if (bk) atomicMax(&g_argmax, bk);
    }
}

// ==================================================================
// Finalize step
// ==================================================================
__global__ __launch_bounds__(512) void kg_final(int t, const float* __restrict__ attn_mem,
                                                const float* __restrict__ attn_v,
                                                float* __restrict__ out) {
    __shared__ float red[32];
    __shared__ float bc;
    int tid = threadIdx.x, lane = tid & 31, w = tid >> 5;
    int done_prev = g_done;
    unsigned long long key = g_argmax;
    int out_idx = NROWS - (int)(unsigned)(key & 0xFFFFFFFFull);
    float sc = htanh(g_feat_a[(size_t)out_idx * 512 + tid] + g_qw2[tid]) * attn_v[tid];
    sc = warp_sum(sc);
    if (lane == 0) red[w] = sc;
    __syncthreads();
    if (tid < 32) {
        float r = (tid < 16) ? red[tid] : 0.f;
        r = warp_sum(r);
        if (tid == 0) bc = r;
    }
    __syncthreads();
    float score_out = bc;
    int new_done = done_prev | (out_idx == STOPIDX);
    if (!new_done) g_x[tid] = attn_mem[(size_t)out_idx * 512 + tid];
    if (tid == 0) {
        float logp = score_out - __logf(g_S);
        out[t] = (float)(done_prev ? STOPIDX : out_idx);
        out[TSTEPS + t] = done_prev ? 0.f : logp;
        if (!done_prev) g_sel[out_idx] = 1;
        g_done = new_done;
        g_argmax = 0ull;
    }
}

// ==================================================================
// Launch
// ==================================================================
extern "C" void kernel_launch(void* const* d_in, const int* in_sizes, int n_in,
                              void* d_out, int out_size) {
    const float* attn_mem = (const float*)d_in[0];
    const float* stop     = (const float*)d_in[1];
    const float* init_h   = (const float*)d_in[2];
    const float* init_c   = (const float*)d_in[3];
    const float* init_i   = (const float*)d_in[4];
    const float* attn_wm  = (const float*)d_in[5];
    const float* attn_wq  = (const float*)d_in[6];
    const float* attn_v   = (const float*)d_in[7];
    const float* hop_wm   = (const float*)d_in[8];
    const float* hop_wq   = (const float*)d_in[9];
    const float* hop_v    = (const float*)d_in[10];
    const float* w_ih     = (const float*)d_in[11];
    const float* w_hh     = (const float*)d_in[12];
    const float* b_ih     = (const float*)d_in[13];
    const float* b_hh     = (const float*)d_in[14];
    const float* gumbel   = (const float*)d_in[15];
    float* out = (float*)d_out;

    kg_init<<<1024, 256>>>(attn_wq, hop_wq, attn_wm, hop_wm, attn_mem, stop,
                           init_h, init_c, init_i);
    kg_gemm<<<dim3(8, NPAD / 128), 256>>>();
    for (int t = 0; t < TSTEPS; t++) {
        kg_gates<<<64, 256>>>(w_ih, w_hh, b_ih, b_hh);
        kg_hcqw<<<64, 256>>>(t & 1);
        kg_hop<<<PB, 256>>>(hop_v);
        kg_qw2<<<64, 256>>>();
        kg_score<<<PB, 256>>>(attn_v, gumbel + (size_t)t * NROWS);
        kg_final<<<1, 512>>>(t, attn_mem, attn_v, out);
    }
}